// round 1
// baseline (speedup 1.0000x reference)
#include <cuda_runtime.h>
#include <math.h>

#define H 8
#define D 128
#define KN 16
#define NNODES 10000
#define FIN 128

// ---- scratch (static device globals; no allocation allowed) ----
__device__ float g_h[H * NNODES * D];      // 41 MB: per-head transformed features
__device__ float g_emb[NNODES * D];        // layer output (5.1 MB)
__device__ float g_ssrc[H * NNODES];
__device__ float g_sdst[H * NNODES];
__device__ float g_gsum[D];

// ============================================================================
// Kernel 1: per-head GEMM h[h][n][:] = W[h] @ X[n], fused with attention score
// dots s_src[h][n] = h·a_src, s_dst[h][n] = h·a_dst.
// Block tile: 128 nodes x 128 dims (full D), BK=16, 256 threads, 8x8/thread.
// ============================================================================
#define BM 128
#define BK 16

__global__ __launch_bounds__(256, 2) void gat_gemm(
    const float* __restrict__ X, const float* __restrict__ W,
    const float* __restrict__ avec)
{
    const int h  = blockIdx.y;
    const int n0 = blockIdx.x * BM;
    const int tid = threadIdx.x;
    const int tx = tid & 15;   // dim group: dims tx*8 .. tx*8+7
    const int ty = tid >> 4;   // node group: nodes n0+ty*8 .. +7

    __shared__ float As[BK][BM + 4];
    __shared__ float Bs[BK][D + 4];

    const float* Wh = W + (size_t)h * D * FIN;

    float acc[8][8];
#pragma unroll
    for (int i = 0; i < 8; i++)
#pragma unroll
        for (int j = 0; j < 8; j++) acc[i][j] = 0.f;

    const int ar = tid >> 1;          // 0..127 (row within tile)
    const int ac = (tid & 1) * 8;     // 0 or 8 (col group within BK)

    for (int kt = 0; kt < FIN; kt += BK) {
        // A tile: X[n0+ar][kt+ac .. +7] (zeros beyond N)
        float4 a0 = make_float4(0.f,0.f,0.f,0.f), a1 = make_float4(0.f,0.f,0.f,0.f);
        if (n0 + ar < NNODES) {
            const float4* p = (const float4*)(X + (size_t)(n0 + ar) * FIN + kt + ac);
            a0 = p[0]; a1 = p[1];
        }
        As[ac+0][ar]=a0.x; As[ac+1][ar]=a0.y; As[ac+2][ar]=a0.z; As[ac+3][ar]=a0.w;
        As[ac+4][ar]=a1.x; As[ac+5][ar]=a1.y; As[ac+6][ar]=a1.z; As[ac+7][ar]=a1.w;
        // B tile: W[h][ar][kt+ac .. +7] stored transposed Bs[f][d]
        {
            const float4* p = (const float4*)(Wh + (size_t)ar * FIN + kt + ac);
            float4 b0 = p[0], b1 = p[1];
            Bs[ac+0][ar]=b0.x; Bs[ac+1][ar]=b0.y; Bs[ac+2][ar]=b0.z; Bs[ac+3][ar]=b0.w;
            Bs[ac+4][ar]=b1.x; Bs[ac+5][ar]=b1.y; Bs[ac+6][ar]=b1.z; Bs[ac+7][ar]=b1.w;
        }
        __syncthreads();
#pragma unroll
        for (int k = 0; k < BK; k++) {
            float ra[8], rb[8];
#pragma unroll
            for (int i = 0; i < 8; i++) ra[i] = As[k][ty*8 + i];
#pragma unroll
            for (int j = 0; j < 8; j++) rb[j] = Bs[k][tx*8 + j];
#pragma unroll
            for (int i = 0; i < 8; i++)
#pragma unroll
                for (int j = 0; j < 8; j++) acc[i][j] += ra[i] * rb[j];
        }
        __syncthreads();
    }

    // Epilogue: write h, compute fused score dots with cross-tx reduction.
    float as_[8], ad_[8];
#pragma unroll
    for (int j = 0; j < 8; j++) {
        as_[j] = avec[h * 2 * D + tx*8 + j];
        ad_[j] = avec[h * 2 * D + D + tx*8 + j];
    }
#pragma unroll
    for (int i = 0; i < 8; i++) {
        const int n = n0 + ty*8 + i;
        float ss = 0.f, sd = 0.f;
#pragma unroll
        for (int j = 0; j < 8; j++) { ss += acc[i][j] * as_[j]; sd += acc[i][j] * ad_[j]; }
        // reduce over the 16 tx lanes (lane = (ty&1)*16 + tx, so xor 8..1 stays in-group)
#pragma unroll
        for (int s = 8; s >= 1; s >>= 1) {
            ss += __shfl_xor_sync(0xffffffffu, ss, s);
            sd += __shfl_xor_sync(0xffffffffu, sd, s);
        }
        if (n < NNODES) {
            if (tx == 0) { g_ssrc[h*NNODES + n] = ss; g_sdst[h*NNODES + n] = sd; }
            float4* po = (float4*)(g_h + ((size_t)h * NNODES + n) * D + tx*8);
            po[0] = make_float4(acc[i][0], acc[i][1], acc[i][2], acc[i][3]);
            po[1] = make_float4(acc[i][4], acc[i][5], acc[i][6], acc[i][7]);
        }
    }
}

// ============================================================================
// Kernel 2: attention. 1 block/node, 1 warp/head.
// e = lrelu(s_src[n] + s_dst[nbr]); alpha = softmax_k; out = sum_k alpha*h[nbr];
// mean over heads, ELU -> g_emb[n].
// ============================================================================
__global__ __launch_bounds__(256) void gat_attn(const int* __restrict__ nbr)
{
    const int n = blockIdx.x;
    const int tid = threadIdx.x;
    __shared__ int nb[KN];
    __shared__ float hacc[H][D];

    if (tid < KN) nb[tid] = nbr[n * KN + tid];
    __syncthreads();

    const int w = tid >> 5, lane = tid & 31;

    float e = -1e30f;
    if (lane < KN) {
        float v = g_ssrc[w * NNODES + n] + g_sdst[w * NNODES + nb[lane]];
        e = v > 0.f ? v : 0.01f * v;
    }
    float mx = e;
#pragma unroll
    for (int s = 16; s >= 1; s >>= 1) mx = fmaxf(mx, __shfl_xor_sync(0xffffffffu, mx, s));
    float ex = (lane < KN) ? expf(e - mx) : 0.f;
    float sum = ex;
#pragma unroll
    for (int s = 16; s >= 1; s >>= 1) sum += __shfl_xor_sync(0xffffffffu, sum, s);
    const float alpha = ex / sum;

    const float* hb = g_h + (size_t)w * NNODES * D;
    float4 acc0 = make_float4(0.f,0.f,0.f,0.f), acc1 = make_float4(0.f,0.f,0.f,0.f);
#pragma unroll
    for (int k = 0; k < KN; k += 2) {
        const float a0 = __shfl_sync(0xffffffffu, alpha, k);
        const float a1 = __shfl_sync(0xffffffffu, alpha, k + 1);
        const float4 v0 = *((const float4*)(hb + (size_t)nb[k]   * D) + lane);
        const float4 v1 = *((const float4*)(hb + (size_t)nb[k+1] * D) + lane);
        acc0.x += a0*v0.x; acc0.y += a0*v0.y; acc0.z += a0*v0.z; acc0.w += a0*v0.w;
        acc1.x += a1*v1.x; acc1.y += a1*v1.y; acc1.z += a1*v1.z; acc1.w += a1*v1.w;
    }
    float4 t = make_float4(acc0.x+acc1.x, acc0.y+acc1.y, acc0.z+acc1.z, acc0.w+acc1.w);
    ((float4*)hacc[w])[lane] = t;
    __syncthreads();

    if (tid < D) {
        float s = 0.f;
#pragma unroll
        for (int hh = 0; hh < H; hh++) s += hacc[hh][tid];
        s *= 0.125f;                       // mean over heads
        s = s > 0.f ? s : expm1f(s);       // ELU (alpha=1)
        g_emb[(size_t)n * D + tid] = s;
    }
}

// ============================================================================
// Final reduce (g = mean over nodes) + tiny MLP
// ============================================================================
__global__ void zero_gsum() { if (threadIdx.x < D) g_gsum[threadIdx.x] = 0.f; }

__global__ void reduce_kernel()
{
    const int d = threadIdx.x;                // 128 threads
    const int ns = blockIdx.x * 128;
    const int ne = min(ns + 128, NNODES);
    float s = 0.f;
    for (int n = ns; n < ne; n++) s += g_emb[(size_t)n * D + d];
    atomicAdd(&g_gsum[d], s);
}

__global__ void mlp_kernel(
    const float* __restrict__ ln1_g, const float* __restrict__ ln1_b,
    const float* __restrict__ lin1_W,
    const float* __restrict__ ln2_g, const float* __restrict__ ln2_b,
    const float* __restrict__ lin2_W, const float* __restrict__ lin2_b,
    const float* __restrict__ ln3_g, const float* __restrict__ ln3_b,
    const float* __restrict__ lin3_W, const float* __restrict__ lin3_b,
    const float* __restrict__ lin4_W, const float* __restrict__ lin4_b,
    float* __restrict__ out)
{
    __shared__ float buf[128];
    __shared__ float stat[2];
    const int t = threadIdx.x;   // 128 threads

    buf[t] = g_gsum[t] * (1.0f / NNODES);
    __syncthreads();

    // LN1 (len 128)
    if (t == 0) { float s=0; for (int i=0;i<128;i++) s+=buf[i]; stat[0]=s/128.f; }
    __syncthreads();
    if (t == 0) { float s=0; for (int i=0;i<128;i++){float d=buf[i]-stat[0]; s+=d*d;} stat[1]=s/128.f; }
    __syncthreads();
    float xv = (buf[t]-stat[0]) * rsqrtf(stat[1]+1e-5f) * ln1_g[t] + ln1_b[t];
    __syncthreads(); buf[t] = xv; __syncthreads();

    // lin1 (64x128, no bias) + exact GELU
    float o = 0.f;
    if (t < 64) {
        for (int d = 0; d < 128; d++) o += buf[d] * lin1_W[t*128 + d];
        o = o * normcdff(o);
    }
    __syncthreads(); if (t < 64) buf[t] = o; __syncthreads();

    // LN2 (len 64)
    if (t == 0) { float s=0; for (int i=0;i<64;i++) s+=buf[i]; stat[0]=s/64.f; }
    __syncthreads();
    if (t == 0) { float s=0; for (int i=0;i<64;i++){float d=buf[i]-stat[0]; s+=d*d;} stat[1]=s/64.f; }
    __syncthreads();
    if (t < 64) xv = (buf[t]-stat[0]) * rsqrtf(stat[1]+1e-5f) * ln2_g[t] + ln2_b[t];
    __syncthreads(); if (t < 64) buf[t] = xv; __syncthreads();

    // lin2 (32x64) + bias + GELU
    if (t < 32) {
        o = lin2_b[t];
        for (int d = 0; d < 64; d++) o += buf[d] * lin2_W[t*64 + d];
        o = o * normcdff(o);
    }
    __syncthreads(); if (t < 32) buf[t] = o; __syncthreads();

    // LN3 (len 32)
    if (t == 0) { float s=0; for (int i=0;i<32;i++) s+=buf[i]; stat[0]=s/32.f; }
    __syncthreads();
    if (t == 0) { float s=0; for (int i=0;i<32;i++){float d=buf[i]-stat[0]; s+=d*d;} stat[1]=s/32.f; }
    __syncthreads();
    if (t < 32) xv = (buf[t]-stat[0]) * rsqrtf(stat[1]+1e-5f) * ln3_g[t] + ln3_b[t];
    __syncthreads(); if (t < 32) buf[t] = xv; __syncthreads();

    // lin3 (8x32) + bias + GELU
    if (t < 8) {
        o = lin3_b[t];
        for (int d = 0; d < 32; d++) o += buf[d] * lin3_W[t*32 + d];
        o = o * normcdff(o);
    }
    __syncthreads(); if (t < 8) buf[t] = o; __syncthreads();

    // lin4 (1x8) + bias + ReLU
    if (t == 0) {
        float r = lin4_b[0];
        for (int i = 0; i < 8; i++) r += buf[i] * lin4_W[i];
        out[0] = fmaxf(r, 0.f);
    }
}

// ============================================================================
extern "C" void kernel_launch(void* const* d_in, const int* in_sizes, int n_in,
                              void* d_out, int out_size)
{
    const float* xf    = (const float*)d_in[0];
    const int*   nbr   = (const int*)  d_in[1];
    const float* W1    = (const float*)d_in[2];
    const float* a1    = (const float*)d_in[3];
    const float* W2    = (const float*)d_in[4];
    const float* a2    = (const float*)d_in[5];
    const float* W3    = (const float*)d_in[6];
    const float* a3    = (const float*)d_in[7];
    const float* ln1_g = (const float*)d_in[8];
    const float* ln1_b = (const float*)d_in[9];
    const float* lin1_W= (const float*)d_in[10];
    const float* ln2_g = (const float*)d_in[11];
    const float* ln2_b = (const float*)d_in[12];
    const float* lin2_W= (const float*)d_in[13];
    const float* lin2_b= (const float*)d_in[14];
    const float* ln3_g = (const float*)d_in[15];
    const float* ln3_b = (const float*)d_in[16];
    const float* lin3_W= (const float*)d_in[17];
    const float* lin3_b= (const float*)d_in[18];
    const float* lin4_W= (const float*)d_in[19];
    const float* lin4_b= (const float*)d_in[20];
    float* out = (float*)d_out;

    float* embp = nullptr;
    cudaGetSymbolAddress((void**)&embp, g_emb);

    const dim3 ggrid((NNODES + BM - 1) / BM, H);   // (79, 8)

    gat_gemm<<<ggrid, 256>>>(xf,   W1, a1);
    gat_attn<<<NNODES, 256>>>(nbr);
    gat_gemm<<<ggrid, 256>>>(embp, W2, a2);
    gat_attn<<<NNODES, 256>>>(nbr);
    gat_gemm<<<ggrid, 256>>>(embp, W3, a3);
    gat_attn<<<NNODES, 256>>>(nbr);

    zero_gsum<<<1, 128>>>();
    reduce_kernel<<<(NNODES + 127) / 128, 128>>>();
    mlp_kernel<<<1, 128>>>(ln1_g, ln1_b, lin1_W, ln2_g, ln2_b, lin2_W, lin2_b,
                           ln3_g, ln3_b, lin3_W, lin3_b, lin4_W, lin4_b, out);
    (void)in_sizes; (void)n_in; (void)out_size;
}

// round 4
// speedup vs baseline: 1.8594x; 1.8594x over previous
#include <cuda_runtime.h>
#include <cuda_bf16.h>
#include <stdint.h>
#include <math.h>

#define H 8
#define D 128
#define KN 16
#define NNODES 10000
#define FIN 128

// ---- scratch (static device globals; no allocation allowed) ----
__device__ __nv_bfloat16 g_h[H * NNODES * D];   // 20.5 MB transformed features (bf16)
__device__ float g_emb[NNODES * D];             // layer output fp32 (5.1 MB)
__device__ float g_ssrc[H * NNODES];
__device__ float g_sdst[H * NNODES];
__device__ float g_gsum[D];

// ============================================================================
// Kernel 1: per-head GEMM via bf16 tensor cores (mma.m16n8k16, fp32 accum),
// fused with attention score dots (computed from fp32 accumulators).
// Block: 128 nodes x 128 dims, BK=32, 256 threads, warp grid 4(m) x 2(n).
// ============================================================================
#define BM 128
#define BK 32
#define ASTRIDE 40   // bf16 elems per row (80B): conflict-free for ldmatrix

__device__ __forceinline__ void mma16816(float* c, const uint32_t* a, const uint32_t* b)
{
    asm volatile(
        "mma.sync.aligned.m16n8k16.row.col.f32.bf16.bf16.f32 "
        "{%0,%1,%2,%3}, {%4,%5,%6,%7}, {%8,%9}, {%0,%1,%2,%3};"
        : "+f"(c[0]), "+f"(c[1]), "+f"(c[2]), "+f"(c[3])
        : "r"(a[0]), "r"(a[1]), "r"(a[2]), "r"(a[3]), "r"(b[0]), "r"(b[1]));
}

__device__ __forceinline__ void ldsm4(uint32_t* r, uint32_t saddr)
{
    asm volatile("ldmatrix.sync.aligned.m8n8.x4.shared.b16 {%0,%1,%2,%3}, [%4];"
                 : "=r"(r[0]), "=r"(r[1]), "=r"(r[2]), "=r"(r[3]) : "r"(saddr));
}

__global__ __launch_bounds__(256, 2) void gat_gemm(
    const float* __restrict__ X, const float* __restrict__ W,
    const float* __restrict__ avec)
{
    const int h  = blockIdx.y;
    const int n0 = blockIdx.x * BM;
    const int tid = threadIdx.x;
    const int wid = tid >> 5, lane = tid & 31;
    const int warp_m = wid >> 1;        // 0..3 -> 32 rows each
    const int warp_n = wid & 1;         // 0..1 -> 64 cols each
    const int g = lane >> 2, t = lane & 3;

    __shared__ __align__(16) __nv_bfloat16 As[BM * ASTRIDE];
    __shared__ __align__(16) __nv_bfloat16 Bs[D * ASTRIDE];
    __shared__ float s_as[D], s_ad[D];
    __shared__ float sss[BM], ssd[BM];

    if (tid < D) {
        s_as[tid] = avec[h * 2 * D + tid];
        s_ad[tid] = avec[h * 2 * D + D + tid];
    }
    if (tid < BM) { sss[tid] = 0.f; ssd[tid] = 0.f; }

    const float* Wh = W + (size_t)h * D * FIN;
    const uint32_t as_base = (uint32_t)__cvta_generic_to_shared(As);
    const uint32_t bs_base = (uint32_t)__cvta_generic_to_shared(Bs);

    float acc[2][8][4];
#pragma unroll
    for (int mt = 0; mt < 2; mt++)
#pragma unroll
        for (int nt = 0; nt < 8; nt++)
#pragma unroll
            for (int i = 0; i < 4; i++) acc[mt][nt][i] = 0.f;

    for (int kt = 0; kt < FIN; kt += BK) {
        // --- load A tile (X rows -> bf16), 4 float4 per thread ---
#pragma unroll
        for (int i = 0; i < 4; i++) {
            const int v = tid + i * 256;          // float4 index 0..1023
            const int row = v >> 3;
            const int c = (v & 7) << 2;           // col (floats/bf16)
            float4 val = make_float4(0.f, 0.f, 0.f, 0.f);
            if (n0 + row < NNODES)
                val = *(const float4*)(X + (size_t)(n0 + row) * FIN + kt + c);
            __nv_bfloat162* dst = (__nv_bfloat162*)&As[row * ASTRIDE + c];
            dst[0] = __floats2bfloat162_rn(val.x, val.y);
            dst[1] = __floats2bfloat162_rn(val.z, val.w);
        }
        // --- load B tile (W[h][d][k] -> Bs[d][k], k-contiguous) ---
#pragma unroll
        for (int i = 0; i < 4; i++) {
            const int v = tid + i * 256;
            const int row = v >> 3;
            const int c = (v & 7) << 2;
            float4 val = *(const float4*)(Wh + (size_t)row * FIN + kt + c);
            __nv_bfloat162* dst = (__nv_bfloat162*)&Bs[row * ASTRIDE + c];
            dst[0] = __floats2bfloat162_rn(val.x, val.y);
            dst[1] = __floats2bfloat162_rn(val.z, val.w);
        }
        __syncthreads();

#pragma unroll
        for (int ks = 0; ks < BK; ks += 16) {
            uint32_t b[8][2];
#pragma unroll
            for (int np = 0; np < 4; np++) {      // n-tile pairs
                const int row = warp_n * 64 + np * 16 + (lane & 7) + ((lane >> 4) << 3);
                const int col = ks + (((lane >> 3) & 1) << 3);
                uint32_t r[4];
                ldsm4(r, bs_base + (uint32_t)(row * ASTRIDE + col) * 2);
                b[2*np][0] = r[0]; b[2*np][1] = r[1];
                b[2*np+1][0] = r[2]; b[2*np+1][1] = r[3];
            }
#pragma unroll
            for (int mt = 0; mt < 2; mt++) {
                const int row = warp_m * 32 + mt * 16 + (lane & 7) + (((lane >> 3) & 1) << 3);
                const int col = ks + ((lane >> 4) << 3);
                uint32_t a[4];
                ldsm4(a, as_base + (uint32_t)(row * ASTRIDE + col) * 2);
#pragma unroll
                for (int nt = 0; nt < 8; nt++) mma16816(acc[mt][nt], a, b[nt]);
            }
        }
        __syncthreads();
    }

    // --- epilogue: scores (fp32) + bf16 h store ---
#pragma unroll
    for (int mt = 0; mt < 2; mt++) {
        float ss0 = 0.f, sd0 = 0.f, ss1 = 0.f, sd1 = 0.f;
#pragma unroll
        for (int nt = 0; nt < 8; nt++) {
            const int c0 = warp_n * 64 + nt * 8 + 2 * t;
            const float as0 = s_as[c0], as1 = s_as[c0 + 1];
            const float ad0 = s_ad[c0], ad1 = s_ad[c0 + 1];
            ss0 += acc[mt][nt][0] * as0 + acc[mt][nt][1] * as1;
            sd0 += acc[mt][nt][0] * ad0 + acc[mt][nt][1] * ad1;
            ss1 += acc[mt][nt][2] * as0 + acc[mt][nt][3] * as1;
            sd1 += acc[mt][nt][2] * ad0 + acc[mt][nt][3] * ad1;
        }
#pragma unroll
        for (int s = 2; s >= 1; s >>= 1) {
            ss0 += __shfl_xor_sync(0xffffffffu, ss0, s);
            sd0 += __shfl_xor_sync(0xffffffffu, sd0, s);
            ss1 += __shfl_xor_sync(0xffffffffu, ss1, s);
            sd1 += __shfl_xor_sync(0xffffffffu, sd1, s);
        }
        if (t == 0) {
            const int r0 = warp_m * 32 + mt * 16 + g;
            atomicAdd(&sss[r0], ss0); atomicAdd(&ssd[r0], sd0);
            atomicAdd(&sss[r0 + 8], ss1); atomicAdd(&ssd[r0 + 8], sd1);
        }
        // h store (bf16x2 per reg pair)
        const int rl0 = warp_m * 32 + mt * 16 + g;
        const int nA = n0 + rl0, nB = nA + 8;
#pragma unroll
        for (int nt = 0; nt < 8; nt++) {
            const int col = warp_n * 64 + nt * 8 + 2 * t;
            if (nA < NNODES)
                *(__nv_bfloat162*)&g_h[((size_t)h * NNODES + nA) * D + col] =
                    __floats2bfloat162_rn(acc[mt][nt][0], acc[mt][nt][1]);
            if (nB < NNODES)
                *(__nv_bfloat162*)&g_h[((size_t)h * NNODES + nB) * D + col] =
                    __floats2bfloat162_rn(acc[mt][nt][2], acc[mt][nt][3]);
        }
    }
    __syncthreads();
    if (tid < BM) {
        const int n = n0 + tid;
        if (n < NNODES) {
            g_ssrc[h * NNODES + n] = sss[tid];
            g_sdst[h * NNODES + n] = ssd[tid];
        }
    }
}

// ============================================================================
// Kernel 2: attention. 1 block/node, 1 warp/head. bf16 gathers (half bytes).
// ============================================================================
__global__ __launch_bounds__(256) void gat_attn(const int* __restrict__ nbr)
{
    const int n = blockIdx.x;
    const int tid = threadIdx.x;
    __shared__ int nb[KN];
    __shared__ float hacc[H][D];

    if (tid < KN) nb[tid] = nbr[n * KN + tid];
    __syncthreads();

    const int w = tid >> 5, lane = tid & 31;

    float e = -1e30f;
    if (lane < KN) {
        float v = g_ssrc[w * NNODES + n] + g_sdst[w * NNODES + nb[lane]];
        e = v > 0.f ? v : 0.01f * v;
    }
    float mx = e;
#pragma unroll
    for (int s = 16; s >= 1; s >>= 1) mx = fmaxf(mx, __shfl_xor_sync(0xffffffffu, mx, s));
    float ex = (lane < KN) ? expf(e - mx) : 0.f;
    float sum = ex;
#pragma unroll
    for (int s = 16; s >= 1; s >>= 1) sum += __shfl_xor_sync(0xffffffffu, sum, s);
    const float alpha = ex / sum;

    const __nv_bfloat16* hb = g_h + (size_t)w * NNODES * D;
    float a0x = 0.f, a0y = 0.f, a0z = 0.f, a0w = 0.f;
    float a1x = 0.f, a1y = 0.f, a1z = 0.f, a1w = 0.f;
#pragma unroll
    for (int k = 0; k < KN; k += 2) {
        const float c0 = __shfl_sync(0xffffffffu, alpha, k);
        const float c1 = __shfl_sync(0xffffffffu, alpha, k + 1);
        const uint2 v0 = *(const uint2*)(hb + (size_t)nb[k]   * D + lane * 4);
        const uint2 v1 = *(const uint2*)(hb + (size_t)nb[k+1] * D + lane * 4);
        const float2 p00 = __bfloat1622float2(*(const __nv_bfloat162*)&v0.x);
        const float2 p01 = __bfloat1622float2(*(const __nv_bfloat162*)&v0.y);
        const float2 p10 = __bfloat1622float2(*(const __nv_bfloat162*)&v1.x);
        const float2 p11 = __bfloat1622float2(*(const __nv_bfloat162*)&v1.y);
        a0x += c0 * p00.x; a0y += c0 * p00.y; a0z += c0 * p01.x; a0w += c0 * p01.y;
        a1x += c1 * p10.x; a1y += c1 * p10.y; a1z += c1 * p11.x; a1w += c1 * p11.y;
    }
    ((float4*)hacc[w])[lane] = make_float4(a0x + a1x, a0y + a1y, a0z + a1z, a0w + a1w);
    __syncthreads();

    if (tid < D) {
        float s = 0.f;
#pragma unroll
        for (int hh = 0; hh < H; hh++) s += hacc[hh][tid];
        s *= 0.125f;                       // mean over heads
        s = s > 0.f ? s : expm1f(s);       // ELU (alpha=1)
        g_emb[(size_t)n * D + tid] = s;
    }
}

// ============================================================================
// Final reduce (g = mean over nodes) + tiny MLP
// ============================================================================
__global__ void zero_gsum() { if (threadIdx.x < D) g_gsum[threadIdx.x] = 0.f; }

__global__ void reduce_kernel()
{
    const int d = threadIdx.x;                // 128 threads
    const int ns = blockIdx.x * 128;
    const int ne = min(ns + 128, NNODES);
    float s = 0.f;
    for (int n = ns; n < ne; n++) s += g_emb[(size_t)n * D + d];
    atomicAdd(&g_gsum[d], s);
}

__global__ void mlp_kernel(
    const float* __restrict__ ln1_g, const float* __restrict__ ln1_b,
    const float* __restrict__ lin1_W,
    const float* __restrict__ ln2_g, const float* __restrict__ ln2_b,
    const float* __restrict__ lin2_W, const float* __restrict__ lin2_b,
    const float* __restrict__ ln3_g, const float* __restrict__ ln3_b,
    const float* __restrict__ lin3_W, const float* __restrict__ lin3_b,
    const float* __restrict__ lin4_W, const float* __restrict__ lin4_b,
    float* __restrict__ out)
{
    __shared__ float buf[128];
    __shared__ float stat[2];
    const int t = threadIdx.x;   // 128 threads

    buf[t] = g_gsum[t] * (1.0f / NNODES);
    __syncthreads();

    // LN1 (len 128)
    if (t == 0) { float s=0; for (int i=0;i<128;i++) s+=buf[i]; stat[0]=s/128.f; }
    __syncthreads();
    if (t == 0) { float s=0; for (int i=0;i<128;i++){float d=buf[i]-stat[0]; s+=d*d;} stat[1]=s/128.f; }
    __syncthreads();
    float xv = (buf[t]-stat[0]) * rsqrtf(stat[1]+1e-5f) * ln1_g[t] + ln1_b[t];
    __syncthreads(); buf[t] = xv; __syncthreads();

    // lin1 (64x128, no bias) + exact GELU
    float o = 0.f;
    if (t < 64) {
        for (int d = 0; d < 128; d++) o += buf[d] * lin1_W[t*128 + d];
        o = o * normcdff(o);
    }
    __syncthreads(); if (t < 64) buf[t] = o; __syncthreads();

    // LN2 (len 64)
    if (t == 0) { float s=0; for (int i=0;i<64;i++) s+=buf[i]; stat[0]=s/64.f; }
    __syncthreads();
    if (t == 0) { float s=0; for (int i=0;i<64;i++){float d=buf[i]-stat[0]; s+=d*d;} stat[1]=s/64.f; }
    __syncthreads();
    if (t < 64) xv = (buf[t]-stat[0]) * rsqrtf(stat[1]+1e-5f) * ln2_g[t] + ln2_b[t];
    __syncthreads(); if (t < 64) buf[t] = xv; __syncthreads();

    // lin2 (32x64) + bias + GELU
    if (t < 32) {
        o = lin2_b[t];
        for (int d = 0; d < 64; d++) o += buf[d] * lin2_W[t*64 + d];
        o = o * normcdff(o);
    }
    __syncthreads(); if (t < 32) buf[t] = o; __syncthreads();

    // LN3 (len 32)
    if (t == 0) { float s=0; for (int i=0;i<32;i++) s+=buf[i]; stat[0]=s/32.f; }
    __syncthreads();
    if (t == 0) { float s=0; for (int i=0;i<32;i++){float d=buf[i]-stat[0]; s+=d*d;} stat[1]=s/32.f; }
    __syncthreads();
    if (t < 32) xv = (buf[t]-stat[0]) * rsqrtf(stat[1]+1e-5f) * ln3_g[t] + ln3_b[t];
    __syncthreads(); if (t < 32) buf[t] = xv; __syncthreads();

    // lin3 (8x32) + bias + GELU
    if (t < 8) {
        o = lin3_b[t];
        for (int d = 0; d < 32; d++) o += buf[d] * lin3_W[t*32 + d];
        o = o * normcdff(o);
    }
    __syncthreads(); if (t < 8) buf[t] = o; __syncthreads();

    // lin4 (1x8) + bias + ReLU
    if (t == 0) {
        float r = lin4_b[0];
        for (int i = 0; i < 8; i++) r += buf[i] * lin4_W[i];
        out[0] = fmaxf(r, 0.f);
    }
}

// ============================================================================
extern "C" void kernel_launch(void* const* d_in, const int* in_sizes, int n_in,
                              void* d_out, int out_size)
{
    const float* xf    = (const float*)d_in[0];
    const int*   nbr   = (const int*)  d_in[1];
    const float* W1    = (const float*)d_in[2];
    const float* a1    = (const float*)d_in[3];
    const float* W2    = (const float*)d_in[4];
    const float* a2    = (const float*)d_in[5];
    const float* W3    = (const float*)d_in[6];
    const float* a3    = (const float*)d_in[7];
    const float* ln1_g = (const float*)d_in[8];
    const float* ln1_b = (const float*)d_in[9];
    const float* lin1_W= (const float*)d_in[10];
    const float* ln2_g = (const float*)d_in[11];
    const float* ln2_b = (const float*)d_in[12];
    const float* lin2_W= (const float*)d_in[13];
    const float* lin2_b= (const float*)d_in[14];
    const float* ln3_g = (const float*)d_in[15];
    const float* ln3_b = (const float*)d_in[16];
    const float* lin3_W= (const float*)d_in[17];
    const float* lin3_b= (const float*)d_in[18];
    const float* lin4_W= (const float*)d_in[19];
    const float* lin4_b= (const float*)d_in[20];
    float* out = (float*)d_out;

    float* embp = nullptr;
    cudaGetSymbolAddress((void**)&embp, g_emb);

    const dim3 ggrid((NNODES + BM - 1) / BM, H);   // (79, 8)

    gat_gemm<<<ggrid, 256>>>(xf,   W1, a1);
    gat_attn<<<NNODES, 256>>>(nbr);
    gat_gemm<<<ggrid, 256>>>(embp, W2, a2);
    gat_attn<<<NNODES, 256>>>(nbr);
    gat_gemm<<<ggrid, 256>>>(embp, W3, a3);
    gat_attn<<<NNODES, 256>>>(nbr);

    zero_gsum<<<1, 128>>>();
    reduce_kernel<<<(NNODES + 127) / 128, 128>>>();
    mlp_kernel<<<1, 128>>>(ln1_g, ln1_b, lin1_W, ln2_g, ln2_b, lin2_W, lin2_b,
                           ln3_g, ln3_b, lin3_W, lin3_b, lin4_W, lin4_b, out);
    (void)in_sizes; (void)n_in; (void)out_size;
}

// round 6
// speedup vs baseline: 2.1766x; 1.1706x over previous
#include <cuda_runtime.h>
#include <cuda_bf16.h>
#include <stdint.h>
#include <math.h>

#define H 8
#define D 128
#define KN 16
#define NNODES 10000
#define FIN 128

// ---- scratch (static device globals; no allocation allowed) ----
__device__ __nv_bfloat16 g_h[H * NNODES * D];      // 20.5 MB transformed features
__device__ __nv_bfloat16 g_ab[NNODES * FIN];       // bf16 X / emb buffer (2.56 MB)
__device__ __nv_bfloat16 g_wb[3 * H * D * FIN];    // bf16 weights (768 KB)
__device__ float g_ssrc[H * NNODES];
__device__ float g_sdst[H * NNODES];
__device__ float g_gsum[D];

// ============================================================================
// fp32 -> bf16 converters (run once per call, trivially cheap)
// ============================================================================
__global__ void cvt_bf16(const float* __restrict__ src, __nv_bfloat16* __restrict__ dst, int n4)
{
    const int i = blockIdx.x * blockDim.x + threadIdx.x;
    if (i < n4) {
        const float4 v = ((const float4*)src)[i];
        __nv_bfloat162* d = (__nv_bfloat162*)(dst + i * 4);
        d[0] = __floats2bfloat162_rn(v.x, v.y);
        d[1] = __floats2bfloat162_rn(v.z, v.w);
    }
}

// ============================================================================
// Kernel 1: per-head GEMM via bf16 tensor cores (mma.m16n8k16, fp32 accum),
// fused score dots. A and B already bf16 in gmem. BK=64 (2 chunks of K=128).
// ============================================================================
#define BM 128
#define BKC 64            // k-chunk held in smem
#define ASTRIDE 72        // bf16 elems per smem row (144B): 16B-aligned, LDSM conflict-free

__device__ __forceinline__ void mma16816(float* c, const uint32_t* a, const uint32_t* b)
{
    asm volatile(
        "mma.sync.aligned.m16n8k16.row.col.f32.bf16.bf16.f32 "
        "{%0,%1,%2,%3}, {%4,%5,%6,%7}, {%8,%9}, {%0,%1,%2,%3};"
        : "+f"(c[0]), "+f"(c[1]), "+f"(c[2]), "+f"(c[3])
        : "r"(a[0]), "r"(a[1]), "r"(a[2]), "r"(a[3]), "r"(b[0]), "r"(b[1]));
}

__device__ __forceinline__ void ldsm4(uint32_t* r, uint32_t saddr)
{
    asm volatile("ldmatrix.sync.aligned.m8n8.x4.shared.b16 {%0,%1,%2,%3}, [%4];"
                 : "=r"(r[0]), "=r"(r[1]), "=r"(r[2]), "=r"(r[3]) : "r"(saddr));
}

__global__ __launch_bounds__(256, 2) void gat_gemm(
    const __nv_bfloat16* __restrict__ A, const __nv_bfloat16* __restrict__ W,
    const float* __restrict__ avec)
{
    const int h  = blockIdx.y;
    const int n0 = blockIdx.x * BM;
    const int tid = threadIdx.x;
    const int wid = tid >> 5, lane = tid & 31;
    const int warp_m = wid >> 1;        // 0..3 -> 32 rows each
    const int warp_n = wid & 1;         // 0..1 -> 64 cols each
    const int g = lane >> 2, t = lane & 3;

    __shared__ __align__(16) __nv_bfloat16 As[BM * ASTRIDE];
    __shared__ __align__(16) __nv_bfloat16 Bs[D * ASTRIDE];
    __shared__ float s_as[D], s_ad[D];
    __shared__ float sss[BM], ssd[BM];

    if (tid < D) {
        s_as[tid] = avec[h * 2 * D + tid];
        s_ad[tid] = avec[h * 2 * D + D + tid];
    }
    if (tid < BM) { sss[tid] = 0.f; ssd[tid] = 0.f; }

    const __nv_bfloat16* Wh = W + (size_t)h * D * FIN;
    const uint32_t as_base = (uint32_t)__cvta_generic_to_shared(As);
    const uint32_t bs_base = (uint32_t)__cvta_generic_to_shared(Bs);

    float acc[2][8][4];
#pragma unroll
    for (int mt = 0; mt < 2; mt++)
#pragma unroll
        for (int nt = 0; nt < 8; nt++)
#pragma unroll
            for (int i = 0; i < 4; i++) acc[mt][nt][i] = 0.f;

    for (int kt = 0; kt < FIN; kt += BKC) {
        // Each k-chunk: 128 rows x 64 cols bf16 = 1024 uint4 chunks per tile.
#pragma unroll
        for (int it = 0; it < 4; it++) {
            const int v = tid + it * 256;
            const int row = v >> 3;
            const int cb = (v & 7) * 8;          // elem col within chunk
            // A tile (zeros beyond N)
            uint4 va = make_uint4(0u, 0u, 0u, 0u);
            if (n0 + row < NNODES)
                va = *(const uint4*)(A + (size_t)(n0 + row) * FIN + kt + cb);
            *(uint4*)&As[row * ASTRIDE + cb] = va;
            // B tile
            *(uint4*)&Bs[row * ASTRIDE + cb] =
                *(const uint4*)(Wh + (size_t)row * FIN + kt + cb);
        }
        __syncthreads();

#pragma unroll
        for (int ks = 0; ks < BKC; ks += 16) {
            uint32_t b[8][2];
#pragma unroll
            for (int np = 0; np < 4; np++) {
                const int row = warp_n * 64 + np * 16 + (lane & 7) + ((lane >> 4) << 3);
                const int col = ks + (((lane >> 3) & 1) << 3);
                uint32_t r[4];
                ldsm4(r, bs_base + (uint32_t)(row * ASTRIDE + col) * 2);
                b[2*np][0] = r[0]; b[2*np][1] = r[1];
                b[2*np+1][0] = r[2]; b[2*np+1][1] = r[3];
            }
#pragma unroll
            for (int mt = 0; mt < 2; mt++) {
                const int row = warp_m * 32 + mt * 16 + (lane & 7) + (((lane >> 3) & 1) << 3);
                const int col = ks + ((lane >> 4) << 3);
                uint32_t a[4];
                ldsm4(a, as_base + (uint32_t)(row * ASTRIDE + col) * 2);
#pragma unroll
                for (int nt = 0; nt < 8; nt++) mma16816(acc[mt][nt], a, b[nt]);
            }
        }
        __syncthreads();
    }

    // --- epilogue: scores (fp32) + bf16 h store ---
#pragma unroll
    for (int mt = 0; mt < 2; mt++) {
        float ss0 = 0.f, sd0 = 0.f, ss1 = 0.f, sd1 = 0.f;
#pragma unroll
        for (int nt = 0; nt < 8; nt++) {
            const int c0 = warp_n * 64 + nt * 8 + 2 * t;
            const float as0 = s_as[c0], as1 = s_as[c0 + 1];
            const float ad0 = s_ad[c0], ad1 = s_ad[c0 + 1];
            ss0 += acc[mt][nt][0] * as0 + acc[mt][nt][1] * as1;
            sd0 += acc[mt][nt][0] * ad0 + acc[mt][nt][1] * ad1;
            ss1 += acc[mt][nt][2] * as0 + acc[mt][nt][3] * as1;
            sd1 += acc[mt][nt][2] * ad0 + acc[mt][nt][3] * ad1;
        }
#pragma unroll
        for (int s = 2; s >= 1; s >>= 1) {
            ss0 += __shfl_xor_sync(0xffffffffu, ss0, s);
            sd0 += __shfl_xor_sync(0xffffffffu, sd0, s);
            ss1 += __shfl_xor_sync(0xffffffffu, ss1, s);
            sd1 += __shfl_xor_sync(0xffffffffu, sd1, s);
        }
        if (t == 0) {
            const int r0 = warp_m * 32 + mt * 16 + g;
            atomicAdd(&sss[r0], ss0); atomicAdd(&ssd[r0], sd0);
            atomicAdd(&sss[r0 + 8], ss1); atomicAdd(&ssd[r0 + 8], sd1);
        }
        const int rl0 = warp_m * 32 + mt * 16 + g;
        const int nA = n0 + rl0, nB = nA + 8;
#pragma unroll
        for (int nt = 0; nt < 8; nt++) {
            const int col = warp_n * 64 + nt * 8 + 2 * t;
            if (nA < NNODES)
                *(__nv_bfloat162*)&g_h[((size_t)h * NNODES + nA) * D + col] =
                    __floats2bfloat162_rn(acc[mt][nt][0], acc[mt][nt][1]);
            if (nB < NNODES)
                *(__nv_bfloat162*)&g_h[((size_t)h * NNODES + nB) * D + col] =
                    __floats2bfloat162_rn(acc[mt][nt][2], acc[mt][nt][3]);
        }
    }
    __syncthreads();
    if (tid < BM) {
        const int n = n0 + tid;
        if (n < NNODES) {
            g_ssrc[h * NNODES + n] = sss[tid];
            g_sdst[h * NNODES + n] = ssd[tid];
        }
    }
}

// ============================================================================
// Kernel 2: attention. 1 block/node, 1 warp/head.
// Half-warp x uint4 gathers, HFMA2 bf16x2 accumulation, 32-bit offsets,
// register-resident neighbor indices (no smem nb, one sync total).
// Writes emb as bf16 into g_ab for the next GEMM / final reduce.
// ============================================================================
__global__ __launch_bounds__(256) void gat_attn(const int* __restrict__ nbr)
{
    const int n = blockIdx.x;
    const int tid = threadIdx.x;
    const int w = tid >> 5, lane = tid & 31;
    __shared__ float hacc[H][D];

    int idx = 0;
    float e = -1e30f;
    if (lane < KN) {
        idx = nbr[n * KN + lane];
        const float v = g_ssrc[w * NNODES + n] + g_sdst[w * NNODES + idx];
        e = v > 0.f ? v : 0.01f * v;
    }
    float mx = e;
#pragma unroll
    for (int s = 16; s >= 1; s >>= 1) mx = fmaxf(mx, __shfl_xor_sync(0xffffffffu, mx, s));
    const float ex = (lane < KN) ? expf(e - mx) : 0.f;
    float sum = ex;
#pragma unroll
    for (int s = 16; s >= 1; s >>= 1) sum += __shfl_xor_sync(0xffffffffu, sum, s);
    const float alpha = ex / sum;

    __nv_bfloat162 abf2 = __float2bfloat162_rn(alpha);
    const uint32_t abits = *reinterpret_cast<uint32_t*>(&abf2);

    const char* hb = (const char*)g_h + (size_t)w * NNODES * D * 2;
    const int sub  = lane >> 4;               // 0/1: which neighbor of the pair
    const int colb = (lane & 15) * 16;        // byte offset within 256B row

    __nv_bfloat162 acc0, acc1, acc2, acc3;
    acc0 = acc1 = acc2 = acc3 = __float2bfloat162_rn(0.f);

#pragma unroll
    for (int i = 0; i < 8; i++) {
        const int src = 2 * i + sub;
        const uint32_t ab = __shfl_sync(0xffffffffu, abits, src);
        const int ix = __shfl_sync(0xffffffffu, idx, src);
        const uint4 v = *(const uint4*)(hb + (((unsigned)ix) << 8) + colb);
        const __nv_bfloat162 av = *reinterpret_cast<const __nv_bfloat162*>(&ab);
        acc0 = __hfma2(av, *(const __nv_bfloat162*)&v.x, acc0);
        acc1 = __hfma2(av, *(const __nv_bfloat162*)&v.y, acc1);
        acc2 = __hfma2(av, *(const __nv_bfloat162*)&v.z, acc2);
        acc3 = __hfma2(av, *(const __nv_bfloat162*)&v.w, acc3);
    }
    // combine the two half-warps (even + odd neighbors)
    {
        uint32_t b0 = *reinterpret_cast<uint32_t*>(&acc0);
        uint32_t b1 = *reinterpret_cast<uint32_t*>(&acc1);
        uint32_t b2 = *reinterpret_cast<uint32_t*>(&acc2);
        uint32_t b3 = *reinterpret_cast<uint32_t*>(&acc3);
        const uint32_t o0 = __shfl_xor_sync(0xffffffffu, b0, 16);
        const uint32_t o1 = __shfl_xor_sync(0xffffffffu, b1, 16);
        const uint32_t o2 = __shfl_xor_sync(0xffffffffu, b2, 16);
        const uint32_t o3 = __shfl_xor_sync(0xffffffffu, b3, 16);
        acc0 = __hadd2(acc0, *(const __nv_bfloat162*)&o0);
        acc1 = __hadd2(acc1, *(const __nv_bfloat162*)&o1);
        acc2 = __hadd2(acc2, *(const __nv_bfloat162*)&o2);
        acc3 = __hadd2(acc3, *(const __nv_bfloat162*)&o3);
    }
    if (lane < 16) {
        const float2 f0 = __bfloat1622float2(acc0);
        const float2 f1 = __bfloat1622float2(acc1);
        const float2 f2 = __bfloat1622float2(acc2);
        const float2 f3 = __bfloat1622float2(acc3);
        const int db = (lane & 15) * 8;
        float4* p = (float4*)&hacc[w][db];
        p[0] = make_float4(f0.x, f0.y, f1.x, f1.y);
        p[1] = make_float4(f2.x, f2.y, f3.x, f3.y);
    }
    __syncthreads();

    if (tid < D) {
        float s = 0.f;
#pragma unroll
        for (int hh = 0; hh < H; hh++) s += hacc[hh][tid];
        s *= 0.125f;                       // mean over heads
        s = s > 0.f ? s : expm1f(s);       // ELU (alpha=1)
        g_ab[(size_t)n * D + tid] = __float2bfloat16(s);
    }
}

// ============================================================================
// Final reduce (g = mean over nodes, emb in bf16) + tiny MLP
// ============================================================================
__global__ void zero_gsum() { if (threadIdx.x < D) g_gsum[threadIdx.x] = 0.f; }

__global__ void reduce_kernel()
{
    const int d = threadIdx.x;                // 128 threads
    const int ns = blockIdx.x * 128;
    const int ne = min(ns + 128, NNODES);
    float s = 0.f;
    for (int n = ns; n < ne; n++) s += __bfloat162float(g_ab[(size_t)n * D + d]);
    atomicAdd(&g_gsum[d], s);
}

__global__ void mlp_kernel(
    const float* __restrict__ ln1_g, const float* __restrict__ ln1_b,
    const float* __restrict__ lin1_W,
    const float* __restrict__ ln2_g, const float* __restrict__ ln2_b,
    const float* __restrict__ lin2_W, const float* __restrict__ lin2_b,
    const float* __restrict__ ln3_g, const float* __restrict__ ln3_b,
    const float* __restrict__ lin3_W, const float* __restrict__ lin3_b,
    const float* __restrict__ lin4_W, const float* __restrict__ lin4_b,
    float* __restrict__ out)
{
    __shared__ float buf[128];
    __shared__ float stat[2];
    const int t = threadIdx.x;   // 128 threads

    buf[t] = g_gsum[t] * (1.0f / NNODES);
    __syncthreads();

    // LN1 (len 128)
    if (t == 0) { float s=0; for (int i=0;i<128;i++) s+=buf[i]; stat[0]=s/128.f; }
    __syncthreads();
    if (t == 0) { float s=0; for (int i=0;i<128;i++){float d=buf[i]-stat[0]; s+=d*d;} stat[1]=s/128.f; }
    __syncthreads();
    float xv = (buf[t]-stat[0]) * rsqrtf(stat[1]+1e-5f) * ln1_g[t] + ln1_b[t];
    __syncthreads(); buf[t] = xv; __syncthreads();

    // lin1 (64x128, no bias) + exact GELU
    float o = 0.f;
    if (t < 64) {
        for (int d = 0; d < 128; d++) o += buf[d] * lin1_W[t*128 + d];
        o = o * normcdff(o);
    }
    __syncthreads(); if (t < 64) buf[t] = o; __syncthreads();

    // LN2 (len 64)
    if (t == 0) { float s=0; for (int i=0;i<64;i++) s+=buf[i]; stat[0]=s/64.f; }
    __syncthreads();
    if (t == 0) { float s=0; for (int i=0;i<64;i++){float d=buf[i]-stat[0]; s+=d*d;} stat[1]=s/64.f; }
    __syncthreads();
    if (t < 64) xv = (buf[t]-stat[0]) * rsqrtf(stat[1]+1e-5f) * ln2_g[t] + ln2_b[t];
    __syncthreads(); if (t < 64) buf[t] = xv; __syncthreads();

    // lin2 (32x64) + bias + GELU
    if (t < 32) {
        o = lin2_b[t];
        for (int d = 0; d < 64; d++) o += buf[d] * lin2_W[t*64 + d];
        o = o * normcdff(o);
    }
    __syncthreads(); if (t < 32) buf[t] = o; __syncthreads();

    // LN3 (len 32)
    if (t == 0) { float s=0; for (int i=0;i<32;i++) s+=buf[i]; stat[0]=s/32.f; }
    __syncthreads();
    if (t == 0) { float s=0; for (int i=0;i<32;i++){float d=buf[i]-stat[0]; s+=d*d;} stat[1]=s/32.f; }
    __syncthreads();
    if (t < 32) xv = (buf[t]-stat[0]) * rsqrtf(stat[1]+1e-5f) * ln3_g[t] + ln3_b[t];
    __syncthreads(); if (t < 32) buf[t] = xv; __syncthreads();

    // lin3 (8x32) + bias + GELU
    if (t < 8) {
        o = lin3_b[t];
        for (int d = 0; d < 32; d++) o += buf[d] * lin3_W[t*32 + d];
        o = o * normcdff(o);
    }
    __syncthreads(); if (t < 8) buf[t] = o; __syncthreads();

    // lin4 (1x8) + bias + ReLU
    if (t == 0) {
        float r = lin4_b[0];
        for (int i = 0; i < 8; i++) r += buf[i] * lin4_W[i];
        out[0] = fmaxf(r, 0.f);
    }
}

// ============================================================================
extern "C" void kernel_launch(void* const* d_in, const int* in_sizes, int n_in,
                              void* d_out, int out_size)
{
    const float* xf    = (const float*)d_in[0];
    const int*   nbr   = (const int*)  d_in[1];
    const float* W1    = (const float*)d_in[2];
    const float* a1    = (const float*)d_in[3];
    const float* W2    = (const float*)d_in[4];
    const float* a2    = (const float*)d_in[5];
    const float* W3    = (const float*)d_in[6];
    const float* a3    = (const float*)d_in[7];
    const float* ln1_g = (const float*)d_in[8];
    const float* ln1_b = (const float*)d_in[9];
    const float* lin1_W= (const float*)d_in[10];
    const float* ln2_g = (const float*)d_in[11];
    const float* ln2_b = (const float*)d_in[12];
    const float* lin2_W= (const float*)d_in[13];
    const float* lin2_b= (const float*)d_in[14];
    const float* ln3_g = (const float*)d_in[15];
    const float* ln3_b = (const float*)d_in[16];
    const float* lin3_W= (const float*)d_in[17];
    const float* lin3_b= (const float*)d_in[18];
    const float* lin4_W= (const float*)d_in[19];
    const float* lin4_b= (const float*)d_in[20];
    float* out = (float*)d_out;

    __nv_bfloat16 *abp = nullptr, *wbp = nullptr;
    cudaGetSymbolAddress((void**)&abp, g_ab);
    cudaGetSymbolAddress((void**)&wbp, g_wb);

    const int WSZ = H * D * FIN;                       // 131072
    // pre-convert X and weights to bf16
    cvt_bf16<<<(NNODES * FIN / 4 + 255) / 256, 256>>>(xf, abp, NNODES * FIN / 4);
    cvt_bf16<<<(WSZ / 4 + 255) / 256, 256>>>(W1, wbp,            WSZ / 4);
    cvt_bf16<<<(WSZ / 4 + 255) / 256, 256>>>(W2, wbp + WSZ,      WSZ / 4);
    cvt_bf16<<<(WSZ / 4 + 255) / 256, 256>>>(W3, wbp + 2 * WSZ,  WSZ / 4);

    const dim3 ggrid((NNODES + BM - 1) / BM, H);   // (79, 8)

    gat_gemm<<<ggrid, 256>>>(abp, wbp,            a1);
    gat_attn<<<NNODES, 256>>>(nbr);
    gat_gemm<<<ggrid, 256>>>(abp, wbp + WSZ,      a2);
    gat_attn<<<NNODES, 256>>>(nbr);
    gat_gemm<<<ggrid, 256>>>(abp, wbp + 2 * WSZ,  a3);
    gat_attn<<<NNODES, 256>>>(nbr);

    zero_gsum<<<1, 128>>>();
    reduce_kernel<<<(NNODES + 127) / 128, 128>>>();
    mlp_kernel<<<1, 128>>>(ln1_g, ln1_b, lin1_W, ln2_g, ln2_b, lin2_W, lin2_b,
                           ln3_g, ln3_b, lin3_W, lin3_b, lin4_W, lin4_b, out);
    (void)in_sizes; (void)n_in; (void)out_size;
}

// round 7
// speedup vs baseline: 2.3467x; 1.0781x over previous
#include <cuda_runtime.h>
#include <cuda_bf16.h>
#include <cuda_fp8.h>
#include <stdint.h>
#include <math.h>

#define H 8
#define D 128
#define KN 16
#define NNODES 10000
#define FIN 128

// ---- scratch (static device globals; no allocation allowed) ----
__device__ unsigned char g_h8[H * NNODES * D];     // 10.2 MB fp8 (e4m3) features
__device__ __nv_bfloat16 g_ab[NNODES * FIN];       // bf16 X / emb buffer (2.56 MB)
__device__ __nv_bfloat16 g_wb[3 * H * D * FIN];    // bf16 weights (768 KB)
__device__ float g_ssrc[H * NNODES];
__device__ float g_sdst[H * NNODES];
__device__ float g_gsum[D];

// ============================================================================
// Merged fp32 -> bf16 converter: X + W1 + W2 + W3 in one launch.
// ============================================================================
#define NX4 (NNODES * FIN / 4)     // 320000 float4s
#define NW4 (H * D * FIN / 4)      // 32768 float4s per weight
__global__ void cvt_all(const float* __restrict__ x,  const float* __restrict__ w1,
                        const float* __restrict__ w2, const float* __restrict__ w3)
{
    const int i = blockIdx.x * blockDim.x + threadIdx.x;
    const float* src; __nv_bfloat16* dst; int j;
    if (i < NX4)               { src = x;  dst = g_ab;                 j = i; }
    else if (i < NX4 + NW4)    { src = w1; dst = g_wb;                 j = i - NX4; }
    else if (i < NX4 + 2*NW4)  { src = w2; dst = g_wb + H*D*FIN;       j = i - NX4 - NW4; }
    else if (i < NX4 + 3*NW4)  { src = w3; dst = g_wb + 2*H*D*FIN;     j = i - NX4 - 2*NW4; }
    else return;
    const float4 v = ((const float4*)src)[j];
    __nv_bfloat162* d = (__nv_bfloat162*)(dst + j * 4);
    d[0] = __floats2bfloat162_rn(v.x, v.y);
    d[1] = __floats2bfloat162_rn(v.z, v.w);
}

// ============================================================================
// Kernel 1: per-head GEMM via bf16 tensor cores (mma.m16n8k16, fp32 accum),
// fused score dots. h stored as fp8 e4m3.
// ============================================================================
#define BM 128
#define BKC 64            // k-chunk held in smem
#define ASTRIDE 72        // bf16 elems per smem row (144B): 16B-aligned, LDSM conflict-free

__device__ __forceinline__ void mma16816(float* c, const uint32_t* a, const uint32_t* b)
{
    asm volatile(
        "mma.sync.aligned.m16n8k16.row.col.f32.bf16.bf16.f32 "
        "{%0,%1,%2,%3}, {%4,%5,%6,%7}, {%8,%9}, {%0,%1,%2,%3};"
        : "+f"(c[0]), "+f"(c[1]), "+f"(c[2]), "+f"(c[3])
        : "r"(a[0]), "r"(a[1]), "r"(a[2]), "r"(a[3]), "r"(b[0]), "r"(b[1]));
}

__device__ __forceinline__ void ldsm4(uint32_t* r, uint32_t saddr)
{
    asm volatile("ldmatrix.sync.aligned.m8n8.x4.shared.b16 {%0,%1,%2,%3}, [%4];"
                 : "=r"(r[0]), "=r"(r[1]), "=r"(r[2]), "=r"(r[3]) : "r"(saddr));
}

__global__ __launch_bounds__(256, 2) void gat_gemm(
    const __nv_bfloat16* __restrict__ A, const __nv_bfloat16* __restrict__ W,
    const float* __restrict__ avec)
{
    const int h  = blockIdx.y;
    const int n0 = blockIdx.x * BM;
    const int tid = threadIdx.x;
    const int wid = tid >> 5, lane = tid & 31;
    const int warp_m = wid >> 1;        // 0..3 -> 32 rows each
    const int warp_n = wid & 1;         // 0..1 -> 64 cols each
    const int g = lane >> 2, t = lane & 3;

    __shared__ __align__(16) __nv_bfloat16 As[BM * ASTRIDE];
    __shared__ __align__(16) __nv_bfloat16 Bs[D * ASTRIDE];
    __shared__ float s_as[D], s_ad[D];
    __shared__ float sss[BM], ssd[BM];

    if (tid < D) {
        s_as[tid] = avec[h * 2 * D + tid];
        s_ad[tid] = avec[h * 2 * D + D + tid];
    }
    if (tid < BM) { sss[tid] = 0.f; ssd[tid] = 0.f; }

    const __nv_bfloat16* Wh = W + (size_t)h * D * FIN;
    const uint32_t as_base = (uint32_t)__cvta_generic_to_shared(As);
    const uint32_t bs_base = (uint32_t)__cvta_generic_to_shared(Bs);

    float acc[2][8][4];
#pragma unroll
    for (int mt = 0; mt < 2; mt++)
#pragma unroll
        for (int nt = 0; nt < 8; nt++)
#pragma unroll
            for (int i = 0; i < 4; i++) acc[mt][nt][i] = 0.f;

    for (int kt = 0; kt < FIN; kt += BKC) {
#pragma unroll
        for (int it = 0; it < 4; it++) {
            const int v = tid + it * 256;
            const int row = v >> 3;
            const int cb = (v & 7) * 8;
            uint4 va = make_uint4(0u, 0u, 0u, 0u);
            if (n0 + row < NNODES)
                va = *(const uint4*)(A + (size_t)(n0 + row) * FIN + kt + cb);
            *(uint4*)&As[row * ASTRIDE + cb] = va;
            *(uint4*)&Bs[row * ASTRIDE + cb] =
                *(const uint4*)(Wh + (size_t)row * FIN + kt + cb);
        }
        __syncthreads();

#pragma unroll
        for (int ks = 0; ks < BKC; ks += 16) {
            uint32_t b[8][2];
#pragma unroll
            for (int np = 0; np < 4; np++) {
                const int row = warp_n * 64 + np * 16 + (lane & 7) + ((lane >> 4) << 3);
                const int col = ks + (((lane >> 3) & 1) << 3);
                uint32_t r[4];
                ldsm4(r, bs_base + (uint32_t)(row * ASTRIDE + col) * 2);
                b[2*np][0] = r[0]; b[2*np][1] = r[1];
                b[2*np+1][0] = r[2]; b[2*np+1][1] = r[3];
            }
#pragma unroll
            for (int mt = 0; mt < 2; mt++) {
                const int row = warp_m * 32 + mt * 16 + (lane & 7) + (((lane >> 3) & 1) << 3);
                const int col = ks + ((lane >> 4) << 3);
                uint32_t a[4];
                ldsm4(a, as_base + (uint32_t)(row * ASTRIDE + col) * 2);
#pragma unroll
                for (int nt = 0; nt < 8; nt++) mma16816(acc[mt][nt], a, b[nt]);
            }
        }
        __syncthreads();
    }

    // --- epilogue: scores (fp32) + fp8 h store ---
#pragma unroll
    for (int mt = 0; mt < 2; mt++) {
        float ss0 = 0.f, sd0 = 0.f, ss1 = 0.f, sd1 = 0.f;
#pragma unroll
        for (int nt = 0; nt < 8; nt++) {
            const int c0 = warp_n * 64 + nt * 8 + 2 * t;
            const float as0 = s_as[c0], as1 = s_as[c0 + 1];
            const float ad0 = s_ad[c0], ad1 = s_ad[c0 + 1];
            ss0 += acc[mt][nt][0] * as0 + acc[mt][nt][1] * as1;
            sd0 += acc[mt][nt][0] * ad0 + acc[mt][nt][1] * ad1;
            ss1 += acc[mt][nt][2] * as0 + acc[mt][nt][3] * as1;
            sd1 += acc[mt][nt][2] * ad0 + acc[mt][nt][3] * ad1;
        }
#pragma unroll
        for (int s = 2; s >= 1; s >>= 1) {
            ss0 += __shfl_xor_sync(0xffffffffu, ss0, s);
            sd0 += __shfl_xor_sync(0xffffffffu, sd0, s);
            ss1 += __shfl_xor_sync(0xffffffffu, ss1, s);
            sd1 += __shfl_xor_sync(0xffffffffu, sd1, s);
        }
        if (t == 0) {
            const int r0 = warp_m * 32 + mt * 16 + g;
            atomicAdd(&sss[r0], ss0); atomicAdd(&ssd[r0], sd0);
            atomicAdd(&sss[r0 + 8], ss1); atomicAdd(&ssd[r0 + 8], sd1);
        }
        const int rl0 = warp_m * 32 + mt * 16 + g;
        const int nA = n0 + rl0, nB = nA + 8;
#pragma unroll
        for (int nt = 0; nt < 8; nt++) {
            const int col = warp_n * 64 + nt * 8 + 2 * t;
            if (nA < NNODES) {
                const unsigned short pA = __nv_cvt_float2_to_fp8x2(
                    make_float2(acc[mt][nt][0], acc[mt][nt][1]), __NV_SATFINITE, __NV_E4M3);
                *(unsigned short*)&g_h8[((size_t)h * NNODES + nA) * D + col] = pA;
            }
            if (nB < NNODES) {
                const unsigned short pB = __nv_cvt_float2_to_fp8x2(
                    make_float2(acc[mt][nt][2], acc[mt][nt][3]), __NV_SATFINITE, __NV_E4M3);
                *(unsigned short*)&g_h8[((size_t)h * NNODES + nB) * D + col] = pB;
            }
        }
    }
    __syncthreads();
    if (tid < BM) {
        const int n = n0 + tid;
        if (n < NNODES) {
            g_ssrc[h * NNODES + n] = sss[tid];
            g_sdst[h * NNODES + n] = ssd[tid];
        }
    }
}

// ============================================================================
// Kernel 2: attention. 1 block/node, 1 warp/head. fp8 gathers (uint2 = 8 elems),
// fp16 HFMA2 accumulation, 32-bit offsets, register neighbor indices.
// ============================================================================
__device__ __forceinline__ __half2 fp8x2_to_h2(unsigned short s)
{
    __half2_raw r = __nv_cvt_fp8x2_to_halfraw2((__nv_fp8x2_storage_t)s, __NV_E4M3);
    return *reinterpret_cast<__half2*>(&r);
}

__global__ __launch_bounds__(256) void gat_attn(const int* __restrict__ nbr)
{
    const int n = blockIdx.x;
    const int tid = threadIdx.x;
    const int w = tid >> 5, lane = tid & 31;
    __shared__ float hacc[H][D];

    int idx = 0;
    float e = -1e30f;
    if (lane < KN) {
        idx = nbr[n * KN + lane];
        const float v = g_ssrc[w * NNODES + n] + g_sdst[w * NNODES + idx];
        e = v > 0.f ? v : 0.01f * v;
    }
    float mx = e;
#pragma unroll
    for (int s = 16; s >= 1; s >>= 1) mx = fmaxf(mx, __shfl_xor_sync(0xffffffffu, mx, s));
    const float ex = (lane < KN) ? expf(e - mx) : 0.f;
    float sum = ex;
#pragma unroll
    for (int s = 16; s >= 1; s >>= 1) sum += __shfl_xor_sync(0xffffffffu, sum, s);
    const float alpha = ex / sum;

    __half2 ah2 = __float2half2_rn(alpha);
    const uint32_t habits = *reinterpret_cast<uint32_t*>(&ah2);

    const unsigned char* hb = g_h8 + (size_t)w * NNODES * D;   // 128 B per row
    const int sub  = lane >> 4;               // 0/1: which neighbor of the pair
    const int colb = (lane & 15) * 8;         // byte offset (8 elems) within 128B row

    __half2 acc0, acc1, acc2, acc3;
    acc0 = acc1 = acc2 = acc3 = __float2half2_rn(0.f);

#pragma unroll
    for (int i = 0; i < 8; i++) {
        const int src = 2 * i + sub;
        const uint32_t ab = __shfl_sync(0xffffffffu, habits, src);
        const int ix = __shfl_sync(0xffffffffu, idx, src);
        const uint2 v = *(const uint2*)(hb + (((unsigned)ix) << 7) + colb);
        const __half2 av = *reinterpret_cast<const __half2*>(&ab);
        acc0 = __hfma2(av, fp8x2_to_h2((unsigned short)(v.x & 0xffffu)), acc0);
        acc1 = __hfma2(av, fp8x2_to_h2((unsigned short)(v.x >> 16)),     acc1);
        acc2 = __hfma2(av, fp8x2_to_h2((unsigned short)(v.y & 0xffffu)), acc2);
        acc3 = __hfma2(av, fp8x2_to_h2((unsigned short)(v.y >> 16)),     acc3);
    }
    // combine the two half-warps (even + odd neighbors)
    {
        uint32_t b0 = *reinterpret_cast<uint32_t*>(&acc0);
        uint32_t b1 = *reinterpret_cast<uint32_t*>(&acc1);
        uint32_t b2 = *reinterpret_cast<uint32_t*>(&acc2);
        uint32_t b3 = *reinterpret_cast<uint32_t*>(&acc3);
        const uint32_t o0 = __shfl_xor_sync(0xffffffffu, b0, 16);
        const uint32_t o1 = __shfl_xor_sync(0xffffffffu, b1, 16);
        const uint32_t o2 = __shfl_xor_sync(0xffffffffu, b2, 16);
        const uint32_t o3 = __shfl_xor_sync(0xffffffffu, b3, 16);
        acc0 = __hadd2(acc0, *(const __half2*)&o0);
        acc1 = __hadd2(acc1, *(const __half2*)&o1);
        acc2 = __hadd2(acc2, *(const __half2*)&o2);
        acc3 = __hadd2(acc3, *(const __half2*)&o3);
    }
    if (lane < 16) {
        const float2 f0 = __half22float2(acc0);
        const float2 f1 = __half22float2(acc1);
        const float2 f2 = __half22float2(acc2);
        const float2 f3 = __half22float2(acc3);
        const int db = (lane & 15) * 8;
        float4* p = (float4*)&hacc[w][db];
        p[0] = make_float4(f0.x, f0.y, f1.x, f1.y);
        p[1] = make_float4(f2.x, f2.y, f3.x, f3.y);
    }
    __syncthreads();

    if (tid < D) {
        float s = 0.f;
#pragma unroll
        for (int hh = 0; hh < H; hh++) s += hacc[hh][tid];
        s *= 0.125f;                       // mean over heads
        s = s > 0.f ? s : expm1f(s);       // ELU (alpha=1)
        g_ab[(size_t)n * D + tid] = __float2bfloat16(s);
    }
}

// ============================================================================
// Final reduce (g = mean over nodes, emb in bf16) + tiny MLP
// ============================================================================
__global__ void zero_gsum() { if (threadIdx.x < D) g_gsum[threadIdx.x] = 0.f; }

__global__ void reduce_kernel()
{
    const int d = threadIdx.x;                // 128 threads
    const int ns = blockIdx.x * 128;
    const int ne = min(ns + 128, NNODES);
    float s = 0.f;
    for (int n = ns; n < ne; n++) s += __bfloat162float(g_ab[(size_t)n * D + d]);
    atomicAdd(&g_gsum[d], s);
}

__global__ void mlp_kernel(
    const float* __restrict__ ln1_g, const float* __restrict__ ln1_b,
    const float* __restrict__ lin1_W,
    const float* __restrict__ ln2_g, const float* __restrict__ ln2_b,
    const float* __restrict__ lin2_W, const float* __restrict__ lin2_b,
    const float* __restrict__ ln3_g, const float* __restrict__ ln3_b,
    const float* __restrict__ lin3_W, const float* __restrict__ lin3_b,
    const float* __restrict__ lin4_W, const float* __restrict__ lin4_b,
    float* __restrict__ out)
{
    __shared__ float buf[128];
    __shared__ float stat[2];
    const int t = threadIdx.x;   // 128 threads

    buf[t] = g_gsum[t] * (1.0f / NNODES);
    __syncthreads();

    // LN1 (len 128)
    if (t == 0) { float s=0; for (int i=0;i<128;i++) s+=buf[i]; stat[0]=s/128.f; }
    __syncthreads();
    if (t == 0) { float s=0; for (int i=0;i<128;i++){float d=buf[i]-stat[0]; s+=d*d;} stat[1]=s/128.f; }
    __syncthreads();
    float xv = (buf[t]-stat[0]) * rsqrtf(stat[1]+1e-5f) * ln1_g[t] + ln1_b[t];
    __syncthreads(); buf[t] = xv; __syncthreads();

    // lin1 (64x128, no bias) + exact GELU
    float o = 0.f;
    if (t < 64) {
        for (int d = 0; d < 128; d++) o += buf[d] * lin1_W[t*128 + d];
        o = o * normcdff(o);
    }
    __syncthreads(); if (t < 64) buf[t] = o; __syncthreads();

    // LN2 (len 64)
    if (t == 0) { float s=0; for (int i=0;i<64;i++) s+=buf[i]; stat[0]=s/64.f; }
    __syncthreads();
    if (t == 0) { float s=0; for (int i=0;i<64;i++){float d=buf[i]-stat[0]; s+=d*d;} stat[1]=s/64.f; }
    __syncthreads();
    if (t < 64) xv = (buf[t]-stat[0]) * rsqrtf(stat[1]+1e-5f) * ln2_g[t] + ln2_b[t];
    __syncthreads(); if (t < 64) buf[t] = xv; __syncthreads();

    // lin2 (32x64) + bias + GELU
    if (t < 32) {
        o = lin2_b[t];
        for (int d = 0; d < 64; d++) o += buf[d] * lin2_W[t*64 + d];
        o = o * normcdff(o);
    }
    __syncthreads(); if (t < 32) buf[t] = o; __syncthreads();

    // LN3 (len 32)
    if (t == 0) { float s=0; for (int i=0;i<32;i++) s+=buf[i]; stat[0]=s/32.f; }
    __syncthreads();
    if (t == 0) { float s=0; for (int i=0;i<32;i++){float d=buf[i]-stat[0]; s+=d*d;} stat[1]=s/32.f; }
    __syncthreads();
    if (t < 32) xv = (buf[t]-stat[0]) * rsqrtf(stat[1]+1e-5f) * ln3_g[t] + ln3_b[t];
    __syncthreads(); if (t < 32) buf[t] = xv; __syncthreads();

    // lin3 (8x32) + bias + GELU
    if (t < 8) {
        o = lin3_b[t];
        for (int d = 0; d < 32; d++) o += buf[d] * lin3_W[t*32 + d];
        o = o * normcdff(o);
    }
    __syncthreads(); if (t < 8) buf[t] = o; __syncthreads();

    // lin4 (1x8) + bias + ReLU
    if (t == 0) {
        float r = lin4_b[0];
        for (int i = 0; i < 8; i++) r += buf[i] * lin4_W[i];
        out[0] = fmaxf(r, 0.f);
    }
}

// ============================================================================
extern "C" void kernel_launch(void* const* d_in, const int* in_sizes, int n_in,
                              void* d_out, int out_size)
{
    const float* xf    = (const float*)d_in[0];
    const int*   nbr   = (const int*)  d_in[1];
    const float* W1    = (const float*)d_in[2];
    const float* a1    = (const float*)d_in[3];
    const float* W2    = (const float*)d_in[4];
    const float* a2    = (const float*)d_in[5];
    const float* W3    = (const float*)d_in[6];
    const float* a3    = (const float*)d_in[7];
    const float* ln1_g = (const float*)d_in[8];
    const float* ln1_b = (const float*)d_in[9];
    const float* lin1_W= (const float*)d_in[10];
    const float* ln2_g = (const float*)d_in[11];
    const float* ln2_b = (const float*)d_in[12];
    const float* lin2_W= (const float*)d_in[13];
    const float* lin2_b= (const float*)d_in[14];
    const float* ln3_g = (const float*)d_in[15];
    const float* ln3_b = (const float*)d_in[16];
    const float* lin3_W= (const float*)d_in[17];
    const float* lin3_b= (const float*)d_in[18];
    const float* lin4_W= (const float*)d_in[19];
    const float* lin4_b= (const float*)d_in[20];
    float* out = (float*)d_out;

    __nv_bfloat16 *abp = nullptr, *wbp = nullptr;
    cudaGetSymbolAddress((void**)&abp, g_ab);
    cudaGetSymbolAddress((void**)&wbp, g_wb);

    const int WSZ = H * D * FIN;                       // 131072
    const int totc = NX4 + 3 * NW4;                    // 418304 float4s
    cvt_all<<<(totc + 255) / 256, 256>>>(xf, W1, W2, W3);

    const dim3 ggrid((NNODES + BM - 1) / BM, H);   // (79, 8)

    gat_gemm<<<ggrid, 256>>>(abp, wbp,            a1);
    gat_attn<<<NNODES, 256>>>(nbr);
    gat_gemm<<<ggrid, 256>>>(abp, wbp + WSZ,      a2);
    gat_attn<<<NNODES, 256>>>(nbr);
    gat_gemm<<<ggrid, 256>>>(abp, wbp + 2 * WSZ,  a3);
    gat_attn<<<NNODES, 256>>>(nbr);

    zero_gsum<<<1, 128>>>();
    reduce_kernel<<<(NNODES + 127) / 128, 128>>>();
    mlp_kernel<<<1, 128>>>(ln1_g, ln1_b, lin1_W, ln2_g, ln2_b, lin2_W, lin2_b,
                           ln3_g, ln3_b, lin3_W, lin3_b, lin4_W, lin4_b, out);
    (void)in_sizes; (void)n_in; (void)out_size;
}

// round 8
// speedup vs baseline: 2.3851x; 1.0164x over previous
#include <cuda_runtime.h>
#include <cuda_bf16.h>
#include <cuda_fp8.h>
#include <stdint.h>
#include <math.h>

#define H 8
#define D 128
#define KN 16
#define NNODES 10000
#define FIN 128

// ---- scratch (static device globals; no allocation allowed) ----
__device__ unsigned char g_h8[H * NNODES * D];     // 10.2 MB fp8 (e4m3) features
__device__ __nv_bfloat16 g_ab[NNODES * FIN];       // bf16 X / emb buffer (2.56 MB)
__device__ __nv_bfloat16 g_wb[3 * H * D * FIN];    // bf16 weights (768 KB)
__device__ float g_ssrc[H * NNODES];
__device__ float g_sdst[H * NNODES];
__device__ float g_gsum[D];

// ============================================================================
// Merged fp32 -> bf16 converter: X + W1 + W2 + W3 in one launch.
// ============================================================================
#define NX4 (NNODES * FIN / 4)     // 320000 float4s
#define NW4 (H * D * FIN / 4)      // 32768 float4s per weight
__global__ void cvt_all(const float* __restrict__ x,  const float* __restrict__ w1,
                        const float* __restrict__ w2, const float* __restrict__ w3)
{
    const int i = blockIdx.x * blockDim.x + threadIdx.x;
    const float* src; __nv_bfloat16* dst; int j;
    if (i < NX4)               { src = x;  dst = g_ab;                 j = i; }
    else if (i < NX4 + NW4)    { src = w1; dst = g_wb;                 j = i - NX4; }
    else if (i < NX4 + 2*NW4)  { src = w2; dst = g_wb + H*D*FIN;       j = i - NX4 - NW4; }
    else if (i < NX4 + 3*NW4)  { src = w3; dst = g_wb + 2*H*D*FIN;     j = i - NX4 - 2*NW4; }
    else return;
    const float4 v = ((const float4*)src)[j];
    __nv_bfloat162* d = (__nv_bfloat162*)(dst + j * 4);
    d[0] = __floats2bfloat162_rn(v.x, v.y);
    d[1] = __floats2bfloat162_rn(v.z, v.w);
}

// ============================================================================
// Kernel 1: per-head GEMM (bf16 mma.m16n8k16, fp32 accum) with a 2-stage
// cp.async pipeline over 4 k-chunks of 32. Fused score dots; fp8 h store.
// ============================================================================
#define BM 128
#define BKC 32            // k-chunk held in smem per stage
#define NCHUNK (FIN / BKC)  // 4
#define ASTRIDE 40        // bf16 elems per smem row (80B): conflict-free for ldmatrix
#define STAGE_ELEMS (BM * ASTRIDE)   // per-stage elems (A or B)

__device__ __forceinline__ void mma16816(float* c, const uint32_t* a, const uint32_t* b)
{
    asm volatile(
        "mma.sync.aligned.m16n8k16.row.col.f32.bf16.bf16.f32 "
        "{%0,%1,%2,%3}, {%4,%5,%6,%7}, {%8,%9}, {%0,%1,%2,%3};"
        : "+f"(c[0]), "+f"(c[1]), "+f"(c[2]), "+f"(c[3])
        : "r"(a[0]), "r"(a[1]), "r"(a[2]), "r"(a[3]), "r"(b[0]), "r"(b[1]));
}

__device__ __forceinline__ void ldsm4(uint32_t* r, uint32_t saddr)
{
    asm volatile("ldmatrix.sync.aligned.m8n8.x4.shared.b16 {%0,%1,%2,%3}, [%4];"
                 : "=r"(r[0]), "=r"(r[1]), "=r"(r[2]), "=r"(r[3]) : "r"(saddr));
}

__device__ __forceinline__ void cp16(uint32_t saddr, const void* gaddr, int srcsz)
{
    asm volatile("cp.async.cg.shared.global [%0], [%1], 16, %2;"
                 :: "r"(saddr), "l"(gaddr), "r"(srcsz));
}

template <int N>
__device__ __forceinline__ void cp_wait()
{
    asm volatile("cp.async.wait_group %0;" :: "n"(N) : "memory");
}

__device__ __forceinline__ void cp_commit()
{
    asm volatile("cp.async.commit_group;" ::: "memory");
}

__global__ __launch_bounds__(256, 2) void gat_gemm(
    const __nv_bfloat16* __restrict__ A, const __nv_bfloat16* __restrict__ W,
    const float* __restrict__ avec)
{
    const int h  = blockIdx.y;
    const int n0 = blockIdx.x * BM;
    const int tid = threadIdx.x;
    const int wid = tid >> 5, lane = tid & 31;
    const int warp_m = wid >> 1;        // 0..3 -> 32 rows each
    const int warp_n = wid & 1;         // 0..1 -> 64 cols each
    const int g = lane >> 2, t = lane & 3;

    __shared__ __align__(16) __nv_bfloat16 As[2][STAGE_ELEMS];
    __shared__ __align__(16) __nv_bfloat16 Bs[2][STAGE_ELEMS];
    __shared__ float s_as[D], s_ad[D];
    __shared__ float sss[BM], ssd[BM];

    if (tid < D) {
        s_as[tid] = avec[h * 2 * D + tid];
        s_ad[tid] = avec[h * 2 * D + D + tid];
    }
    if (tid < BM) { sss[tid] = 0.f; ssd[tid] = 0.f; }

    const __nv_bfloat16* Wh = W + (size_t)h * D * FIN;
    const uint32_t as_base = (uint32_t)__cvta_generic_to_shared(&As[0][0]);
    const uint32_t bs_base = (uint32_t)__cvta_generic_to_shared(&Bs[0][0]);
    const uint32_t stage_bytes = STAGE_ELEMS * 2;

    // per-thread copy coords: 2 x 16B per tile per chunk
    // v = tid + it*256 in [0,512): row = v>>2 (0..127), cb = (v&3)*8 elems
    const int prow0 = tid >> 2,            pcb0 = (tid & 3) * 8;
    const int prow1 = (tid + 256) >> 2,    pcb1 = ((tid + 256) & 3) * 8;
    const bool av0 = (n0 + prow0) < NNODES;
    const bool av1 = (n0 + prow1) < NNODES;
    const __nv_bfloat16* arow0 = A + (size_t)(n0 + prow0) * FIN + pcb0;
    const __nv_bfloat16* arow1 = A + (size_t)(n0 + prow1) * FIN + pcb1;
    const __nv_bfloat16* brow0 = Wh + (size_t)prow0 * FIN + pcb0;
    const __nv_bfloat16* brow1 = Wh + (size_t)prow1 * FIN + pcb1;
    const uint32_t soff0 = (uint32_t)(prow0 * ASTRIDE + pcb0) * 2;
    const uint32_t soff1 = (uint32_t)(prow1 * ASTRIDE + pcb1) * 2;

    // prefetch helper (macro-ish lambda)
    auto prefetch = [&](int chunk, int buf) {
        const int kt = chunk * BKC;
        const uint32_t bo = buf * stage_bytes;
        cp16(as_base + bo + soff0, arow0 + kt, av0 ? 16 : 0);
        cp16(as_base + bo + soff1, arow1 + kt, av1 ? 16 : 0);
        cp16(bs_base + bo + soff0, brow0 + kt, 16);
        cp16(bs_base + bo + soff1, brow1 + kt, 16);
        cp_commit();
    };

    float acc[2][8][4];
#pragma unroll
    for (int mt = 0; mt < 2; mt++)
#pragma unroll
        for (int nt = 0; nt < 8; nt++)
#pragma unroll
            for (int i = 0; i < 4; i++) acc[mt][nt][i] = 0.f;

    prefetch(0, 0);
    prefetch(1, 1);

#pragma unroll
    for (int c = 0; c < NCHUNK; c++) {
        const int buf = c & 1;
        if (c == NCHUNK - 1) cp_wait<0>(); else cp_wait<1>();
        __syncthreads();

        const uint32_t abuf = as_base + buf * stage_bytes;
        const uint32_t bbuf = bs_base + buf * stage_bytes;
#pragma unroll
        for (int ks = 0; ks < BKC; ks += 16) {
            uint32_t b[8][2];
#pragma unroll
            for (int np = 0; np < 4; np++) {
                const int row = warp_n * 64 + np * 16 + (lane & 7) + ((lane >> 4) << 3);
                const int col = ks + (((lane >> 3) & 1) << 3);
                uint32_t r[4];
                ldsm4(r, bbuf + (uint32_t)(row * ASTRIDE + col) * 2);
                b[2*np][0] = r[0]; b[2*np][1] = r[1];
                b[2*np+1][0] = r[2]; b[2*np+1][1] = r[3];
            }
#pragma unroll
            for (int mt = 0; mt < 2; mt++) {
                const int row = warp_m * 32 + mt * 16 + (lane & 7) + (((lane >> 3) & 1) << 3);
                const int col = ks + ((lane >> 4) << 3);
                uint32_t a[4];
                ldsm4(a, abuf + (uint32_t)(row * ASTRIDE + col) * 2);
#pragma unroll
                for (int nt = 0; nt < 8; nt++) mma16816(acc[mt][nt], a, b[nt]);
            }
        }

        if (c + 2 < NCHUNK) {
            __syncthreads();          // all warps done reading buf before overwrite
            prefetch(c + 2, buf);
        }
    }

    // --- epilogue: scores (fp32) + fp8 h store ---
#pragma unroll
    for (int mt = 0; mt < 2; mt++) {
        float ss0 = 0.f, sd0 = 0.f, ss1 = 0.f, sd1 = 0.f;
#pragma unroll
        for (int nt = 0; nt < 8; nt++) {
            const int c0 = warp_n * 64 + nt * 8 + 2 * t;
            const float as0 = s_as[c0], as1 = s_as[c0 + 1];
            const float ad0 = s_ad[c0], ad1 = s_ad[c0 + 1];
            ss0 += acc[mt][nt][0] * as0 + acc[mt][nt][1] * as1;
            sd0 += acc[mt][nt][0] * ad0 + acc[mt][nt][1] * ad1;
            ss1 += acc[mt][nt][2] * as0 + acc[mt][nt][3] * as1;
            sd1 += acc[mt][nt][2] * ad0 + acc[mt][nt][3] * ad1;
        }
#pragma unroll
        for (int s = 2; s >= 1; s >>= 1) {
            ss0 += __shfl_xor_sync(0xffffffffu, ss0, s);
            sd0 += __shfl_xor_sync(0xffffffffu, sd0, s);
            ss1 += __shfl_xor_sync(0xffffffffu, ss1, s);
            sd1 += __shfl_xor_sync(0xffffffffu, sd1, s);
        }
        if (t == 0) {
            const int r0 = warp_m * 32 + mt * 16 + g;
            atomicAdd(&sss[r0], ss0); atomicAdd(&ssd[r0], sd0);
            atomicAdd(&sss[r0 + 8], ss1); atomicAdd(&ssd[r0 + 8], sd1);
        }
        const int rl0 = warp_m * 32 + mt * 16 + g;
        const int nA = n0 + rl0, nB = nA + 8;
#pragma unroll
        for (int nt = 0; nt < 8; nt++) {
            const int col = warp_n * 64 + nt * 8 + 2 * t;
            if (nA < NNODES) {
                const unsigned short pA = __nv_cvt_float2_to_fp8x2(
                    make_float2(acc[mt][nt][0], acc[mt][nt][1]), __NV_SATFINITE, __NV_E4M3);
                *(unsigned short*)&g_h8[((size_t)h * NNODES + nA) * D + col] = pA;
            }
            if (nB < NNODES) {
                const unsigned short pB = __nv_cvt_float2_to_fp8x2(
                    make_float2(acc[mt][nt][2], acc[mt][nt][3]), __NV_SATFINITE, __NV_E4M3);
                *(unsigned short*)&g_h8[((size_t)h * NNODES + nB) * D + col] = pB;
            }
        }
    }
    __syncthreads();
    if (tid < BM) {
        const int n = n0 + tid;
        if (n < NNODES) {
            g_ssrc[h * NNODES + n] = sss[tid];
            g_sdst[h * NNODES + n] = ssd[tid];
        }
    }
}

// ============================================================================
// Kernel 2: attention. 1 block/node, 1 warp/head. fp8 gathers (uint2 = 8 elems),
// fp16 HFMA2 accumulation, 32-bit offsets, register neighbor indices.
// ============================================================================
__device__ __forceinline__ __half2 fp8x2_to_h2(unsigned short s)
{
    __half2_raw r = __nv_cvt_fp8x2_to_halfraw2((__nv_fp8x2_storage_t)s, __NV_E4M3);
    return *reinterpret_cast<__half2*>(&r);
}

__global__ __launch_bounds__(256) void gat_attn(const int* __restrict__ nbr)
{
    const int n = blockIdx.x;
    const int tid = threadIdx.x;
    const int w = tid >> 5, lane = tid & 31;
    __shared__ float hacc[H][D];

    int idx = 0;
    float e = -1e30f;
    if (lane < KN) {
        idx = nbr[n * KN + lane];
        const float v = g_ssrc[w * NNODES + n] + g_sdst[w * NNODES + idx];
        e = v > 0.f ? v : 0.01f * v;
    }
    float mx = e;
#pragma unroll
    for (int s = 16; s >= 1; s >>= 1) mx = fmaxf(mx, __shfl_xor_sync(0xffffffffu, mx, s));
    const float ex = (lane < KN) ? expf(e - mx) : 0.f;
    float sum = ex;
#pragma unroll
    for (int s = 16; s >= 1; s >>= 1) sum += __shfl_xor_sync(0xffffffffu, sum, s);
    const float alpha = ex / sum;

    __half2 ah2 = __float2half2_rn(alpha);
    const uint32_t habits = *reinterpret_cast<uint32_t*>(&ah2);

    const unsigned char* hb = g_h8 + (size_t)w * NNODES * D;   // 128 B per row
    const int sub  = lane >> 4;               // 0/1: which neighbor of the pair
    const int colb = (lane & 15) * 8;         // byte offset (8 elems) within 128B row

    __half2 acc0, acc1, acc2, acc3;
    acc0 = acc1 = acc2 = acc3 = __float2half2_rn(0.f);

#pragma unroll
    for (int i = 0; i < 8; i++) {
        const int src = 2 * i + sub;
        const uint32_t ab = __shfl_sync(0xffffffffu, habits, src);
        const int ix = __shfl_sync(0xffffffffu, idx, src);
        const uint2 v = *(const uint2*)(hb + (((unsigned)ix) << 7) + colb);
        const __half2 av = *reinterpret_cast<const __half2*>(&ab);
        acc0 = __hfma2(av, fp8x2_to_h2((unsigned short)(v.x & 0xffffu)), acc0);
        acc1 = __hfma2(av, fp8x2_to_h2((unsigned short)(v.x >> 16)),     acc1);
        acc2 = __hfma2(av, fp8x2_to_h2((unsigned short)(v.y & 0xffffu)), acc2);
        acc3 = __hfma2(av, fp8x2_to_h2((unsigned short)(v.y >> 16)),     acc3);
    }
    // combine the two half-warps (even + odd neighbors)
    {
        uint32_t b0 = *reinterpret_cast<uint32_t*>(&acc0);
        uint32_t b1 = *reinterpret_cast<uint32_t*>(&acc1);
        uint32_t b2 = *reinterpret_cast<uint32_t*>(&acc2);
        uint32_t b3 = *reinterpret_cast<uint32_t*>(&acc3);
        const uint32_t o0 = __shfl_xor_sync(0xffffffffu, b0, 16);
        const uint32_t o1 = __shfl_xor_sync(0xffffffffu, b1, 16);
        const uint32_t o2 = __shfl_xor_sync(0xffffffffu, b2, 16);
        const uint32_t o3 = __shfl_xor_sync(0xffffffffu, b3, 16);
        acc0 = __hadd2(acc0, *(const __half2*)&o0);
        acc1 = __hadd2(acc1, *(const __half2*)&o1);
        acc2 = __hadd2(acc2, *(const __half2*)&o2);
        acc3 = __hadd2(acc3, *(const __half2*)&o3);
    }
    if (lane < 16) {
        const float2 f0 = __half22float2(acc0);
        const float2 f1 = __half22float2(acc1);
        const float2 f2 = __half22float2(acc2);
        const float2 f3 = __half22float2(acc3);
        const int db = (lane & 15) * 8;
        float4* p = (float4*)&hacc[w][db];
        p[0] = make_float4(f0.x, f0.y, f1.x, f1.y);
        p[1] = make_float4(f2.x, f2.y, f3.x, f3.y);
    }
    __syncthreads();

    if (tid < D) {
        float s = 0.f;
#pragma unroll
        for (int hh = 0; hh < H; hh++) s += hacc[hh][tid];
        s *= 0.125f;                       // mean over heads
        s = s > 0.f ? s : expm1f(s);       // ELU (alpha=1)
        g_ab[(size_t)n * D + tid] = __float2bfloat16(s);
    }
}

// ============================================================================
// Final reduce (g = mean over nodes, emb in bf16) + tiny MLP
// ============================================================================
__global__ void zero_gsum() { if (threadIdx.x < D) g_gsum[threadIdx.x] = 0.f; }

__global__ void reduce_kernel()
{
    const int d = threadIdx.x;                // 128 threads
    const int ns = blockIdx.x * 128;
    const int ne = min(ns + 128, NNODES);
    float s = 0.f;
    for (int n = ns; n < ne; n++) s += __bfloat162float(g_ab[(size_t)n * D + d]);
    atomicAdd(&g_gsum[d], s);
}

__global__ void mlp_kernel(
    const float* __restrict__ ln1_g, const float* __restrict__ ln1_b,
    const float* __restrict__ lin1_W,
    const float* __restrict__ ln2_g, const float* __restrict__ ln2_b,
    const float* __restrict__ lin2_W, const float* __restrict__ lin2_b,
    const float* __restrict__ ln3_g, const float* __restrict__ ln3_b,
    const float* __restrict__ lin3_W, const float* __restrict__ lin3_b,
    const float* __restrict__ lin4_W, const float* __restrict__ lin4_b,
    float* __restrict__ out)
{
    __shared__ float buf[128];
    __shared__ float stat[2];
    const int t = threadIdx.x;   // 128 threads

    buf[t] = g_gsum[t] * (1.0f / NNODES);
    __syncthreads();

    // LN1 (len 128)
    if (t == 0) { float s=0; for (int i=0;i<128;i++) s+=buf[i]; stat[0]=s/128.f; }
    __syncthreads();
    if (t == 0) { float s=0; for (int i=0;i<128;i++){float d=buf[i]-stat[0]; s+=d*d;} stat[1]=s/128.f; }
    __syncthreads();
    float xv = (buf[t]-stat[0]) * rsqrtf(stat[1]+1e-5f) * ln1_g[t] + ln1_b[t];
    __syncthreads(); buf[t] = xv; __syncthreads();

    // lin1 (64x128, no bias) + exact GELU
    float o = 0.f;
    if (t < 64) {
        for (int d = 0; d < 128; d++) o += buf[d] * lin1_W[t*128 + d];
        o = o * normcdff(o);
    }
    __syncthreads(); if (t < 64) buf[t] = o; __syncthreads();

    // LN2 (len 64)
    if (t == 0) { float s=0; for (int i=0;i<64;i++) s+=buf[i]; stat[0]=s/64.f; }
    __syncthreads();
    if (t == 0) { float s=0; for (int i=0;i<64;i++){float d=buf[i]-stat[0]; s+=d*d;} stat[1]=s/64.f; }
    __syncthreads();
    if (t < 64) xv = (buf[t]-stat[0]) * rsqrtf(stat[1]+1e-5f) * ln2_g[t] + ln2_b[t];
    __syncthreads(); if (t < 64) buf[t] = xv; __syncthreads();

    // lin2 (32x64) + bias + GELU
    if (t < 32) {
        o = lin2_b[t];
        for (int d = 0; d < 64; d++) o += buf[d] * lin2_W[t*64 + d];
        o = o * normcdff(o);
    }
    __syncthreads(); if (t < 32) buf[t] = o; __syncthreads();

    // LN3 (len 32)
    if (t == 0) { float s=0; for (int i=0;i<32;i++) s+=buf[i]; stat[0]=s/32.f; }
    __syncthreads();
    if (t == 0) { float s=0; for (int i=0;i<32;i++){float d=buf[i]-stat[0]; s+=d*d;} stat[1]=s/32.f; }
    __syncthreads();
    if (t < 32) xv = (buf[t]-stat[0]) * rsqrtf(stat[1]+1e-5f) * ln3_g[t] + ln3_b[t];
    __syncthreads(); if (t < 32) buf[t] = xv; __syncthreads();

    // lin3 (8x32) + bias + GELU
    if (t < 8) {
        o = lin3_b[t];
        for (int d = 0; d < 32; d++) o += buf[d] * lin3_W[t*32 + d];
        o = o * normcdff(o);
    }
    __syncthreads(); if (t < 8) buf[t] = o; __syncthreads();

    // lin4 (1x8) + bias + ReLU
    if (t == 0) {
        float r = lin4_b[0];
        for (int i = 0; i < 8; i++) r += buf[i] * lin4_W[i];
        out[0] = fmaxf(r, 0.f);
    }
}

// ============================================================================
extern "C" void kernel_launch(void* const* d_in, const int* in_sizes, int n_in,
                              void* d_out, int out_size)
{
    const float* xf    = (const float*)d_in[0];
    const int*   nbr   = (const int*)  d_in[1];
    const float* W1    = (const float*)d_in[2];
    const float* a1    = (const float*)d_in[3];
    const float* W2    = (const float*)d_in[4];
    const float* a2    = (const float*)d_in[5];
    const float* W3    = (const float*)d_in[6];
    const float* a3    = (const float*)d_in[7];
    const float* ln1_g = (const float*)d_in[8];
    const float* ln1_b = (const float*)d_in[9];
    const float* lin1_W= (const float*)d_in[10];
    const float* ln2_g = (const float*)d_in[11];
    const float* ln2_b = (const float*)d_in[12];
    const float* lin2_W= (const float*)d_in[13];
    const float* lin2_b= (const float*)d_in[14];
    const float* ln3_g = (const float*)d_in[15];
    const float* ln3_b = (const float*)d_in[16];
    const float* lin3_W= (const float*)d_in[17];
    const float* lin3_b= (const float*)d_in[18];
    const float* lin4_W= (const float*)d_in[19];
    const float* lin4_b= (const float*)d_in[20];
    float* out = (float*)d_out;

    __nv_bfloat16 *abp = nullptr, *wbp = nullptr;
    cudaGetSymbolAddress((void**)&abp, g_ab);
    cudaGetSymbolAddress((void**)&wbp, g_wb);

    const int WSZ = H * D * FIN;                       // 131072
    const int totc = NX4 + 3 * NW4;                    // 418304 float4s
    cvt_all<<<(totc + 255) / 256, 256>>>(xf, W1, W2, W3);

    const dim3 ggrid((NNODES + BM - 1) / BM, H);   // (79, 8)

    gat_gemm<<<ggrid, 256>>>(abp, wbp,            a1);
    gat_attn<<<NNODES, 256>>>(nbr);
    gat_gemm<<<ggrid, 256>>>(abp, wbp + WSZ,      a2);
    gat_attn<<<NNODES, 256>>>(nbr);
    gat_gemm<<<ggrid, 256>>>(abp, wbp + 2 * WSZ,  a3);
    gat_attn<<<NNODES, 256>>>(nbr);

    zero_gsum<<<1, 128>>>();
    reduce_kernel<<<(NNODES + 127) / 128, 128>>>();
    mlp_kernel<<<1, 128>>>(ln1_g, ln1_b, lin1_W, ln2_g, ln2_b, lin2_W, lin2_b,
                           ln3_g, ln3_b, lin3_W, lin3_b, lin4_W, lin4_b, out);
    (void)in_sizes; (void)n_in; (void)out_size;
}